// round 13
// baseline (speedup 1.0000x reference)
#include <cuda_runtime.h>
#include <cuda_bf16.h>
#include <stdint.h>
#include <math.h>

#define Nn   8192
#define FIN  128
#define Hh   8
#define Cc   128
#define HCd  1024
#define Gg   16
#define NPGd 512
#define Ee   131072
#define Et   (Ee + Nn)   // 139264 edges incl. self loops

// ---------------- scratch (device globals: allocation-free) ----------------
__device__ float g_lin [Nn * HCd];   // h = x @ W^T (pre-bias)
__device__ float g_feat[Nn * HCd];   // normalized h2
__device__ float g_als [Nn * Hh];
__device__ float g_ald [Nn * Hh];
__device__ float g_gs  [Nn * 32];    // node MLP output
__device__ int   g_deg [Nn];
__device__ int   g_off [Nn + 1];
__device__ int   g_cur [Nn];
__device__ int   g_src [Et];         // CSR src lists (by dst)
__device__ __nv_bfloat16 g_A3[Nn  * 3 * HCd];   // split-bf16 A
__device__ __nv_bfloat16 g_B3[HCd * 3 * HCd];   // split-bf16 B

// ================= warp-mma helpers ========================================
__device__ __forceinline__ uint32_t smem_u32(const void* p) {
    uint32_t a;
    asm("{ .reg .u64 t; cvta.to.shared.u64 t, %1; cvt.u32.u64 %0, t; }" : "=r"(a) : "l"(p));
    return a;
}
__device__ __forceinline__ void cp16(uint32_t saddr, const void* g) {
    asm volatile("cp.async.cg.shared.global [%0], [%1], 16;" :: "r"(saddr), "l"(g));
}
#define CP_COMMIT() asm volatile("cp.async.commit_group;" ::: "memory")
#define CP_WAIT(n)  asm volatile("cp.async.wait_group %0;" :: "n"(n) : "memory")

__device__ __forceinline__ void ldsm_x4(uint32_t* r, uint32_t addr) {
    asm volatile("ldmatrix.sync.aligned.m8n8.x4.shared.b16 {%0,%1,%2,%3}, [%4];"
        : "=r"(r[0]), "=r"(r[1]), "=r"(r[2]), "=r"(r[3]) : "r"(addr));
}
__device__ __forceinline__ void mma16816(float* c, const uint32_t* a, uint32_t b0, uint32_t b1) {
    asm volatile(
        "mma.sync.aligned.m16n8k16.row.col.f32.bf16.bf16.f32 "
        "{%0,%1,%2,%3}, {%4,%5,%6,%7}, {%8,%9}, {%0,%1,%2,%3};"
        : "+f"(c[0]), "+f"(c[1]), "+f"(c[2]), "+f"(c[3])
        : "r"(a[0]), "r"(a[1]), "r"(a[2]), "r"(a[3]), "r"(b0), "r"(b1));
}

// ================= split-bf16 tensor-core GEMM (4-stage pipeline) ==========
// C[M,1024] = A3[M,Kp] * B3[1024,Kp]^T, bf16 in, fp32 acc.
// 128x128 block tile, BK=32, 128 threads (4 warps, 64m x 64n each --
// minimizes LDSM bytes/MAC: smem crossbar is the binding resource).
#define GSTR   80                    // smem row stride bytes (64B data + 16B pad)
#define STG_SZ (128 * GSTR)          // 10240B per tensor per stage
#define GT_DSMEM (4 * 2 * STG_SZ)    // 81920B

__global__ __launch_bounds__(128, 2) void gemm_mma(
    const __nv_bfloat16* __restrict__ A, const __nv_bfloat16* __restrict__ B,
    float* __restrict__ C, int Kp)
{
    extern __shared__ unsigned char dsm[];
    const uint32_t sA = smem_u32(dsm);
    const uint32_t sB = sA + 4 * STG_SZ;

    const int tid  = threadIdx.x;
    const int wid  = tid >> 5;
    const int lane = tid & 31;
    const int wm = wid & 1;          // 0..1 -> m offset 64*wm
    const int wn = wid >> 1;         // 0..1 -> n offset 64*wn
    const int bm = blockIdx.y * 128;
    const int bn = blockIdx.x * 128;

    float acc[4][8][4];
#pragma unroll
    for (int i = 0; i < 4; i++)
#pragma unroll
        for (int j = 0; j < 8; j++)
#pragma unroll
            for (int q = 0; q < 4; q++) acc[i][j][q] = 0.0f;

    const int nk = Kp >> 5;

#define LOAD_TILE(kt, stg) do { \
    int _k0 = (kt) << 5; \
    uint32_t _a = sA + (stg) * STG_SZ; \
    uint32_t _b = sB + (stg) * STG_SZ; \
    _Pragma("unroll") \
    for (int _i = 0; _i < 4; _i++) { \
        int _c = tid + _i * 128; \
        int _r = _c >> 2, _f = _c & 3; \
        cp16(_a + _r * GSTR + _f * 16, A + (size_t)(bm + _r) * Kp + _k0 + _f * 8); \
        cp16(_b + _r * GSTR + _f * 16, B + (size_t)(bn + _r) * Kp + _k0 + _f * 8); \
    } \
} while (0)

#pragma unroll
    for (int s = 0; s < 3; s++) { LOAD_TILE(s, s); CP_COMMIT(); }

    const int arow_in = (lane & 7) + 8 * ((lane >> 3) & 1);
    const int akoff   = (lane >> 4) * 16;
    const int brow_in = (lane & 7) + 8 * (lane >> 4);
    const int bkoff   = ((lane >> 3) & 1) * 16;

    for (int kt = 0; kt < nk; kt++) {
        CP_WAIT(2);
        __syncthreads();
        const int stg = kt & 3;
        const uint32_t curA = sA + stg * STG_SZ;
        const uint32_t curB = sB + stg * STG_SZ;

        if (kt + 3 < nk) LOAD_TILE(kt + 3, (kt + 3) & 3);
        CP_COMMIT();

#pragma unroll
        for (int ks = 0; ks < 2; ks++) {
            uint32_t a[4][4], b[4][4];
#pragma unroll
            for (int mt = 0; mt < 4; mt++) {
                int row = wm * 64 + mt * 16 + arow_in;
                ldsm_x4(a[mt], curA + row * GSTR + ks * 32 + akoff);
            }
#pragma unroll
            for (int nt2 = 0; nt2 < 4; nt2++) {
                int row = wn * 64 + nt2 * 16 + brow_in;
                ldsm_x4(b[nt2], curB + row * GSTR + ks * 32 + bkoff);
            }
#pragma unroll
            for (int mt = 0; mt < 4; mt++)
#pragma unroll
                for (int nt2 = 0; nt2 < 4; nt2++) {
                    mma16816(acc[mt][nt2 * 2],     a[mt], b[nt2][0], b[nt2][1]);
                    mma16816(acc[mt][nt2 * 2 + 1], a[mt], b[nt2][2], b[nt2][3]);
                }
        }
    }

    const int qrow = lane >> 2;
    const int qcol = (lane & 3) * 2;
#pragma unroll
    for (int mt = 0; mt < 4; mt++) {
#pragma unroll
        for (int nt = 0; nt < 8; nt++) {
            int row = bm + wm * 64 + mt * 16 + qrow;
            int col = bn + wn * 64 + nt * 8 + qcol;
            *(float2*)(C + (size_t)row * HCd + col)       = make_float2(acc[mt][nt][0], acc[mt][nt][1]);
            *(float2*)(C + (size_t)(row + 8) * HCd + col) = make_float2(acc[mt][nt][2], acc[mt][nt][3]);
        }
    }
}

// ---------------- fp32 -> split-bf16 conversion ----------------------------
// mode 0 (A): [hi | lo | hi]; mode 1 (B): [hi | hi | lo]
__global__ __launch_bounds__(256) void k_split(
    const float* __restrict__ S, __nv_bfloat16* __restrict__ D3, int K, int total, int mode)
{
    int i = (blockIdx.x * 256 + threadIdx.x) * 4;
    if (i >= total) return;
    float4 v = *(const float4*)(S + i);
    int m = i / K, k = i - m * K;
    __nv_bfloat16 h[4], l[4];
    float vv[4] = {v.x, v.y, v.z, v.w};
#pragma unroll
    for (int q = 0; q < 4; q++) {
        h[q] = __float2bfloat16(vv[q]);
        l[q] = __float2bfloat16(vv[q] - __bfloat162float(h[q]));
    }
    size_t base = (size_t)m * 3 * K + k;
    __nv_bfloat162 h01, h23, l01, l23;
    h01.x = h[0]; h01.y = h[1]; h23.x = h[2]; h23.y = h[3];
    l01.x = l[0]; l01.y = l[1]; l23.x = l[2]; l23.y = l[3];
    *(__nv_bfloat162*)(D3 + base)     = h01;
    *(__nv_bfloat162*)(D3 + base + 2) = h23;
    if (mode == 0) {
        *(__nv_bfloat162*)(D3 + base + K)         = l01;
        *(__nv_bfloat162*)(D3 + base + K + 2)     = l23;
        *(__nv_bfloat162*)(D3 + base + 2 * K)     = h01;
        *(__nv_bfloat162*)(D3 + base + 2 * K + 2) = h23;
    } else {
        *(__nv_bfloat162*)(D3 + base + K)         = h01;
        *(__nv_bfloat162*)(D3 + base + K + 2)     = h23;
        *(__nv_bfloat162*)(D3 + base + 2 * K)     = l01;
        *(__nv_bfloat162*)(D3 + base + 2 * K + 2) = l23;
    }
}

// ---------------- CSR build -------------------------------------------------
__global__ void k_zero_deg() {
    int i = blockIdx.x * blockDim.x + threadIdx.x;
    if (i < Nn) g_deg[i] = 0;
}

__global__ __launch_bounds__(256) void k_hist(const int* __restrict__ ei) {
    int e = blockIdx.x * blockDim.x + threadIdx.x;
    if (e >= Et) return;
    int d = (e < Ee) ? ei[Ee + e] : (e - Ee);
    atomicAdd(&g_deg[d], 1);
}

__global__ __launch_bounds__(1024) void k_scan() {
    __shared__ int sh[1024];
    int tid = threadIdx.x;
    int base = tid * 8;
    int loc[8];
    int s = 0;
#pragma unroll
    for (int i = 0; i < 8; i++) { loc[i] = s; s += g_deg[base + i]; }
    sh[tid] = s;
    __syncthreads();
    for (int o = 1; o < 1024; o <<= 1) {
        int v = (tid >= o) ? sh[tid - o] : 0;
        __syncthreads();
        sh[tid] += v;
        __syncthreads();
    }
    int pre = tid ? sh[tid - 1] : 0;
#pragma unroll
    for (int i = 0; i < 8; i++) {
        g_off[base + i] = pre + loc[i];
        g_cur[base + i] = pre + loc[i];
    }
    if (tid == 1023) g_off[Nn] = sh[1023];
}

__global__ __launch_bounds__(256) void k_scatter(const int* __restrict__ ei) {
    int e = blockIdx.x * blockDim.x + threadIdx.x;
    if (e >= Et) return;
    int s, d;
    if (e < Ee) { s = ei[e]; d = ei[Ee + e]; } else { s = d = e - Ee; }
    int pos = atomicAdd(&g_cur[d], 1);
    g_src[pos] = s;
}

// ---------------- attention scalars: als/ald [N,H] -------------------------
__global__ __launch_bounds__(256) void k_alphas(
    const float* __restrict__ h, const float* __restrict__ asrc,
    const float* __restrict__ adst)
{
    int w = (blockIdx.x * blockDim.x + threadIdx.x) >> 5;
    int lane = threadIdx.x & 31;
    if (w >= Nn * Hh) return;
    int n = w >> 3, hd = w & 7;
    const float* hp = h + (size_t)n * HCd + hd * Cc;
    const float* sp = asrc + hd * Cc;
    const float* dp = adst + hd * Cc;
    float s1 = 0.0f, s2 = 0.0f;
#pragma unroll
    for (int c = lane; c < Cc; c += 32) {
        float v = hp[c];
        s1 = fmaf(v, sp[c], s1);
        s2 = fmaf(v, dp[c], s2);
    }
#pragma unroll
    for (int o = 16; o; o >>= 1) {
        s1 += __shfl_down_sync(0xffffffffu, s1, o);
        s2 += __shfl_down_sync(0xffffffffu, s2, o);
    }
    if (lane == 0) { g_als[w] = s1; g_ald[w] = s2; }
}

// ---------------- fused softmax + gather aggregation (block per dst) -------
#define CHUNK 64
__global__ __launch_bounds__(256) void k_agg(
    const float* __restrict__ h, const float* __restrict__ bias,
    float* __restrict__ outp, __nv_bfloat16* __restrict__ A3out, int do_norm)
{
    __shared__ int   ssrc[CHUNK];
    __shared__ float salp[CHUNK * 8];
    __shared__ float red[256];
    __shared__ float sm_m[8], sm_iz[8], sm_ald[8];

    int n = blockIdx.x;
    int t = threadIdx.x;
    int st = g_off[n], en = g_off[n + 1];
    int hd = t >> 5;
    int lane = t & 31;

    // ---- pass 1: online softmax stats, warp w handles head w ----
    float aldh = g_ald[n * Hh + hd];
    float m = -3.0e38f, z = 0.0f;
    for (int j = st + lane; j < en; j += 32) {
        int s = g_src[j];
        float l = g_als[s * Hh + hd] + aldh;
        l = (l > 0.0f) ? l : 0.2f * l;
        float mn = fmaxf(m, l);
        z = z * __expf(m - mn) + __expf(l - mn);
        m = mn;
    }
#pragma unroll
    for (int o = 16; o; o >>= 1) {
        float mo = __shfl_xor_sync(0xffffffffu, m, o);
        float zo = __shfl_xor_sync(0xffffffffu, z, o);
        float mn = fmaxf(m, mo);
        z = z * __expf(m - mn) + zo * __expf(mo - mn);
        m = mn;
    }
    if (lane == 0) {
        sm_m[hd]  = m;
        sm_iz[hd] = 1.0f / (z + 1e-16f);
        sm_ald[hd] = aldh;
    }
    __syncthreads();

    // ---- pass 2: chunked aggregation with on-the-fly alphas ----
    float4 acc = make_float4(0.0f, 0.0f, 0.0f, 0.0f);

    for (int j0 = st; j0 < en; j0 += CHUNK) {
        int cnt = min(CHUNK, en - j0);
        __syncthreads();
        if (t < cnt) ssrc[t] = g_src[j0 + t];
        __syncthreads();
        for (int i = t; i < cnt * 8; i += 256) {
            int e = i >> 3, hh2 = i & 7;
            int s = ssrc[e];
            float l = g_als[s * Hh + hh2] + sm_ald[hh2];
            l = (l > 0.0f) ? l : 0.2f * l;
            salp[i] = __expf(l - sm_m[hh2]) * sm_iz[hh2];
        }
        __syncthreads();
#pragma unroll 2
        for (int i = 0; i < cnt; i++) {
            float a = salp[i * 8 + hd];
            float4 v = ((const float4*)(h + (size_t)ssrc[i] * HCd))[t];
            acc.x = fmaf(a, v.x, acc.x);
            acc.y = fmaf(a, v.y, acc.y);
            acc.z = fmaf(a, v.z, acc.z);
            acc.w = fmaf(a, v.w, acc.w);
        }
    }

    float4 b = ((const float4*)bias)[t];
    acc.x = fmaxf(acc.x + b.x, 0.0f);
    acc.y = fmaxf(acc.y + b.y, 0.0f);
    acc.z = fmaxf(acc.z + b.z, 0.0f);
    acc.w = fmaxf(acc.w + b.w, 0.0f);

    if (A3out) {
        float vv[4] = {acc.x, acc.y, acc.z, acc.w};
        __nv_bfloat16 hi[4], lo[4];
#pragma unroll
        for (int q = 0; q < 4; q++) {
            hi[q] = __float2bfloat16(vv[q]);
            lo[q] = __float2bfloat16(vv[q] - __bfloat162float(hi[q]));
        }
        __nv_bfloat162 h01, h23, l01, l23;
        h01.x = hi[0]; h01.y = hi[1]; h23.x = hi[2]; h23.y = hi[3];
        l01.x = lo[0]; l01.y = lo[1]; l23.x = lo[2]; l23.y = lo[3];
        size_t base = (size_t)n * (3 * HCd) + t * 4;
        *(__nv_bfloat162*)(A3out + base)               = h01;
        *(__nv_bfloat162*)(A3out + base + 2)           = h23;
        *(__nv_bfloat162*)(A3out + base + HCd)         = l01;
        *(__nv_bfloat162*)(A3out + base + HCd + 2)     = l23;
        *(__nv_bfloat162*)(A3out + base + 2 * HCd)     = h01;
        *(__nv_bfloat162*)(A3out + base + 2 * HCd + 2) = h23;
        return;
    }

    if (do_norm) {
        float s = acc.x * acc.x + acc.y * acc.y + acc.z * acc.z + acc.w * acc.w;
        red[t] = s;
        __syncthreads();
        for (int o = 128; o; o >>= 1) {
            if (t < o) red[t] += red[t + o];
            __syncthreads();
        }
        float nrm = fmaxf(sqrtf(red[0]), 1e-12f);
        float iv = 1.0f / nrm;
        acc.x *= iv; acc.y *= iv; acc.z *= iv; acc.w *= iv;
    }

    ((float4*)(outp + (size_t)n * HCd))[t] = acc;
}

// ---------------- node MLP: hn[1024] -> 32 -> 32 -> 32 (relu) --------------
__global__ __launch_bounds__(256) void k_small_mlp(
    const float* __restrict__ hn,
    const float* __restrict__ Ws1, const float* __restrict__ bs1,
    const float* __restrict__ Ws2, const float* __restrict__ bs2,
    const float* __restrict__ Ws3, const float* __restrict__ bs3)
{
    __shared__ float wst[32][33];
    int lane = threadIdx.x & 31;
    int wrp  = threadIdx.x >> 5;
    int n = blockIdx.x * 8 + wrp;
    const float* row = hn + (size_t)n * HCd;

    float acc = bs1[lane];
    int j  = threadIdx.x >> 3;
    int kk = threadIdx.x & 7;
    for (int k0 = 0; k0 < HCd; k0 += 32) {
        __syncthreads();
        wst[kk +  0][j] = Ws1[j * HCd + k0 + kk +  0];
        wst[kk +  8][j] = Ws1[j * HCd + k0 + kk +  8];
        wst[kk + 16][j] = Ws1[j * HCd + k0 + kk + 16];
        wst[kk + 24][j] = Ws1[j * HCd + k0 + kk + 24];
        __syncthreads();
        float rv = row[k0 + lane];
#pragma unroll
        for (int q = 0; q < 32; q++) {
            float r = __shfl_sync(0xffffffffu, rv, q);
            acc = fmaf(r, wst[q][lane], acc);
        }
    }
    acc = fmaxf(acc, 0.0f);

    float a2 = bs2[lane];
#pragma unroll
    for (int i = 0; i < 32; i++)
        a2 = fmaf(Ws2[lane * 32 + i], __shfl_sync(0xffffffffu, acc, i), a2);
    a2 = fmaxf(a2, 0.0f);

    float a3 = bs3[lane];
#pragma unroll
    for (int i = 0; i < 32; i++)
        a3 = fmaf(Ws3[lane * 32 + i], __shfl_sync(0xffffffffu, a2, i), a3);
    a3 = fmaxf(a3, 0.0f);

    g_gs[n * 32 + lane] = a3;
}

// ---------------- per-graph Gram: HH[g][d][e] ------------------------------
__global__ __launch_bounds__(1024) void k_gram(float* __restrict__ out) {
    int g = blockIdx.x;
    __shared__ float sg[128][33];
    int d  = threadIdx.x >> 5;
    int e1 = threadIdx.x & 31;
    float acc = 0.0f;
    for (int n0 = 0; n0 < NPGd; n0 += 128) {
        __syncthreads();
        for (int i = threadIdx.x; i < 128 * 32; i += 1024) {
            int r = i >> 5, c = i & 31;
            sg[r][c] = g_gs[(size_t)(g * NPGd + n0 + r) * 32 + c];
        }
        __syncthreads();
#pragma unroll 8
        for (int r = 0; r < 128; r++) acc = fmaf(sg[r][d], sg[r][e1], acc);
    }
    out[g * 1024 + d * 32 + e1] = acc;
}

// ---------------- head MLP: HH[1024] -> 32 -> 32 -> 2 ----------------------
__global__ __launch_bounds__(32) void k_head_mlp(
    const float* __restrict__ HHin,
    const float* __restrict__ Wm1, const float* __restrict__ bm1,
    const float* __restrict__ Wm2, const float* __restrict__ bm2,
    const float* __restrict__ Wm3, const float* __restrict__ bm3,
    float* __restrict__ oout)
{
    int g = blockIdx.x;
    int jj = threadIdx.x;
    const float* hh = HHin + g * 1024;
    float acc = bm1[jj];
    for (int k = 0; k < 1024; k++) acc = fmaf(hh[k], Wm1[jj * 1024 + k], acc);
    acc = fmaxf(acc, 0.0f);

    float a2 = bm2[jj];
#pragma unroll
    for (int i = 0; i < 32; i++)
        a2 = fmaf(Wm2[jj * 32 + i], __shfl_sync(0xffffffffu, acc, i), a2);
    a2 = fmaxf(a2, 0.0f);

    float a3 = (jj < 2) ? bm3[jj] : 0.0f;
#pragma unroll
    for (int i = 0; i < 32; i++) {
        float v = __shfl_sync(0xffffffffu, a2, i);
        if (jj < 2) a3 = fmaf(Wm3[jj * 32 + i], v, a3);
    }
    if (jj < 2) oout[g * 2 + jj] = fmaxf(a3, 0.0f);
}

// ---------------- launch ----------------------------------------------------
extern "C" void kernel_launch(void* const* d_in, const int* in_sizes, int n_in,
                              void* d_out, int out_size)
{
    const float* x   = (const float*)d_in[0];
    const int*   ei  = (const int*)  d_in[1];
    const float* W1  = (const float*)d_in[2];
    const float* as1 = (const float*)d_in[3];
    const float* ad1 = (const float*)d_in[4];
    const float* b1  = (const float*)d_in[5];
    const float* W2  = (const float*)d_in[6];
    const float* as2 = (const float*)d_in[7];
    const float* ad2 = (const float*)d_in[8];
    const float* b2  = (const float*)d_in[9];
    const float* Ws1 = (const float*)d_in[10];
    const float* bs1 = (const float*)d_in[11];
    const float* Ws2 = (const float*)d_in[12];
    const float* bs2 = (const float*)d_in[13];
    const float* Ws3 = (const float*)d_in[14];
    const float* bs3 = (const float*)d_in[15];
    const float* Wm1 = (const float*)d_in[16];
    const float* bm1 = (const float*)d_in[17];
    const float* Wm2 = (const float*)d_in[18];
    const float* bm2 = (const float*)d_in[19];
    const float* Wm3 = (const float*)d_in[20];
    const float* bm3 = (const float*)d_in[21];
    float* out = (float*)d_out;

    float *lin, *feat;
    __nv_bfloat16 *A3, *B3;
    cudaGetSymbolAddress((void**)&lin,  g_lin);
    cudaGetSymbolAddress((void**)&feat, g_feat);
    cudaGetSymbolAddress((void**)&A3,   g_A3);
    cudaGetSymbolAddress((void**)&B3,   g_B3);
    (void)in_sizes; (void)n_in; (void)out_size;

    static int attr_done = 0;
    if (!attr_done) {
        cudaFuncSetAttribute(gemm_mma, cudaFuncAttributeMaxDynamicSharedMemorySize, GT_DSMEM);
        attr_done = 1;
    }

    const int EB = (Et + 255) / 256;

    // ---- CSR build ----
    k_zero_deg<<<(Nn + 255) / 256, 256>>>();
    k_hist<<<EB, 256>>>(ei);
    k_scan<<<1, 1024>>>();
    k_scatter<<<EB, 256>>>(ei);

    // ---- GAT layer 1 ----
    k_split<<<(Nn * FIN / 4 + 255) / 256, 256>>>(x,  A3, FIN, Nn * FIN, 0);
    k_split<<<(HCd * FIN / 4 + 255) / 256, 256>>>(W1, B3, FIN, HCd * FIN, 1);
    gemm_mma<<<dim3(HCd / 128, Nn / 128), 128, GT_DSMEM>>>(A3, B3, lin, 3 * FIN);
    k_alphas<<<(Nn * Hh * 32) / 256, 256>>>(lin, as1, ad1);
    k_agg<<<Nn, 256>>>(lin, b1, nullptr, A3, 0);   // fused softmax; split-bf16 h1 out

    // ---- GAT layer 2 (K' = 3072) ----
    k_split<<<(HCd * HCd / 4 + 255) / 256, 256>>>(W2, B3, HCd, HCd * HCd, 1);
    gemm_mma<<<dim3(HCd / 128, Nn / 128), 128, GT_DSMEM>>>(A3, B3, lin, 3 * HCd);
    k_alphas<<<(Nn * Hh * 32) / 256, 256>>>(lin, as2, ad2);
    k_agg<<<Nn, 256>>>(lin, b2, feat, nullptr, 1); // fused softmax; normalize + fp32

    // ---- node MLP + Gram + head MLP ----
    k_small_mlp<<<Nn / 8, 256>>>(feat, Ws1, bs1, Ws2, bs2, Ws3, bs3);
    k_gram<<<Gg, 1024>>>(out);
    k_head_mlp<<<Gg, 32>>>(out, Wm1, bm1, Wm2, bm2, Wm3, bm3, out + Gg * 1024);
}

// round 17
// speedup vs baseline: 1.5406x; 1.5406x over previous
#include <cuda_runtime.h>
#include <cuda_bf16.h>
#include <stdint.h>
#include <math.h>

#define Nn   8192
#define FIN  128
#define Hh   8
#define Cc   128
#define HCd  1024
#define Gg   16
#define NPGd 512
#define Ee   131072
#define Et   (Ee + Nn)   // 139264 edges incl. self loops

// ---------------- scratch (device globals: allocation-free) ----------------
__device__ float g_lin [Nn * HCd];   // h = x @ W^T (pre-bias)
__device__ float g_feat[Nn * HCd];   // normalized h2
__device__ float g_als [Nn * Hh];
__device__ float g_ald [Nn * Hh];
__device__ float g_gs  [Nn * 32];    // node MLP output
__device__ int   g_deg [Nn];
__device__ int   g_off [Nn + 1];
__device__ int   g_cur [Nn];
__device__ int   g_src [Et];         // CSR src lists (by dst)
__device__ __nv_bfloat16 g_A3 [Nn  * 3 * HCd];   // split-bf16 A
__device__ __nv_bfloat16 g_B3 [HCd * 3 * HCd];   // split-bf16 B (layer 1: W1)
__device__ __nv_bfloat16 g_B3b[HCd * 3 * HCd];   // split-bf16 B (layer 2: W2)

// ================= warp-mma helpers ========================================
__device__ __forceinline__ uint32_t smem_u32(const void* p) {
    uint32_t a;
    asm("{ .reg .u64 t; cvta.to.shared.u64 t, %1; cvt.u32.u64 %0, t; }" : "=r"(a) : "l"(p));
    return a;
}
__device__ __forceinline__ void cp16(uint32_t saddr, const void* g) {
    asm volatile("cp.async.cg.shared.global [%0], [%1], 16;" :: "r"(saddr), "l"(g));
}
#define CP_COMMIT() asm volatile("cp.async.commit_group;" ::: "memory")
#define CP_WAIT(n)  asm volatile("cp.async.wait_group %0;" :: "n"(n) : "memory")

__device__ __forceinline__ void ldsm_x4(uint32_t* r, uint32_t addr) {
    asm volatile("ldmatrix.sync.aligned.m8n8.x4.shared.b16 {%0,%1,%2,%3}, [%4];"
        : "=r"(r[0]), "=r"(r[1]), "=r"(r[2]), "=r"(r[3]) : "r"(addr));
}
__device__ __forceinline__ void mma16816(float* c, const uint32_t* a, uint32_t b0, uint32_t b1) {
    asm volatile(
        "mma.sync.aligned.m16n8k16.row.col.f32.bf16.bf16.f32 "
        "{%0,%1,%2,%3}, {%4,%5,%6,%7}, {%8,%9}, {%0,%1,%2,%3};"
        : "+f"(c[0]), "+f"(c[1]), "+f"(c[2]), "+f"(c[3])
        : "r"(a[0]), "r"(a[1]), "r"(a[2]), "r"(a[3]), "r"(b0), "r"(b1));
}

// ================= split-bf16 tensor-core GEMM (4-stage pipeline) ==========
// C[M,1024] = A3[M,Kp] * B3[1024,Kp]^T, bf16 in, fp32 acc.
// 128x128 tile, BK=32, 256 threads (8 warps, 32m x 64n each). [R11 config]
#define GSTR   80                    // smem row stride bytes (64B data + 16B pad)
#define STG_SZ (128 * GSTR)          // 10240B per tensor per stage
#define GT_DSMEM (4 * 2 * STG_SZ)    // 81920B

__global__ __launch_bounds__(256, 2) void gemm_mma(
    const __nv_bfloat16* __restrict__ A, const __nv_bfloat16* __restrict__ B,
    float* __restrict__ C, int Kp)
{
    extern __shared__ unsigned char dsm[];
    const uint32_t sA = smem_u32(dsm);
    const uint32_t sB = sA + 4 * STG_SZ;

    const int tid  = threadIdx.x;
    const int wid  = tid >> 5;
    const int lane = tid & 31;
    const int wm = wid & 3;
    const int wn = wid >> 2;
    const int bm = blockIdx.y * 128;
    const int bn = blockIdx.x * 128;

    float acc[2][8][4];
#pragma unroll
    for (int i = 0; i < 2; i++)
#pragma unroll
        for (int j = 0; j < 8; j++)
#pragma unroll
            for (int q = 0; q < 4; q++) acc[i][j][q] = 0.0f;

    const int nk = Kp >> 5;

    const int lr0 = tid >> 2,         lf0 = tid & 3;
    const int lr1 = (tid + 256) >> 2, lf1 = (tid + 256) & 3;

#define LOAD_TILE(kt, stg) do { \
    int _k0 = (kt) << 5; \
    uint32_t _a = sA + (stg) * STG_SZ; \
    uint32_t _b = sB + (stg) * STG_SZ; \
    cp16(_a + lr0 * GSTR + lf0 * 16, A + (size_t)(bm + lr0) * Kp + _k0 + lf0 * 8); \
    cp16(_a + lr1 * GSTR + lf1 * 16, A + (size_t)(bm + lr1) * Kp + _k0 + lf1 * 8); \
    cp16(_b + lr0 * GSTR + lf0 * 16, B + (size_t)(bn + lr0) * Kp + _k0 + lf0 * 8); \
    cp16(_b + lr1 * GSTR + lf1 * 16, B + (size_t)(bn + lr1) * Kp + _k0 + lf1 * 8); \
} while (0)

#pragma unroll
    for (int s = 0; s < 3; s++) { LOAD_TILE(s, s); CP_COMMIT(); }

    const int arow_in = (lane & 7) + 8 * ((lane >> 3) & 1);
    const int akoff   = (lane >> 4) * 16;
    const int brow_in = (lane & 7) + 8 * (lane >> 4);
    const int bkoff   = ((lane >> 3) & 1) * 16;

    for (int kt = 0; kt < nk; kt++) {
        CP_WAIT(2);
        __syncthreads();
        const int stg = kt & 3;
        const uint32_t curA = sA + stg * STG_SZ;
        const uint32_t curB = sB + stg * STG_SZ;

        if (kt + 3 < nk) LOAD_TILE(kt + 3, (kt + 3) & 3);
        CP_COMMIT();

#pragma unroll
        for (int ks = 0; ks < 2; ks++) {
            uint32_t a[2][4], b[4][4];
#pragma unroll
            for (int mt = 0; mt < 2; mt++) {
                int row = wm * 32 + mt * 16 + arow_in;
                ldsm_x4(a[mt], curA + row * GSTR + ks * 32 + akoff);
            }
#pragma unroll
            for (int nt2 = 0; nt2 < 4; nt2++) {
                int row = wn * 64 + nt2 * 16 + brow_in;
                ldsm_x4(b[nt2], curB + row * GSTR + ks * 32 + bkoff);
            }
#pragma unroll
            for (int mt = 0; mt < 2; mt++)
#pragma unroll
                for (int nt2 = 0; nt2 < 4; nt2++) {
                    mma16816(acc[mt][nt2 * 2],     a[mt], b[nt2][0], b[nt2][1]);
                    mma16816(acc[mt][nt2 * 2 + 1], a[mt], b[nt2][2], b[nt2][3]);
                }
        }
    }

    const int qrow = lane >> 2;
    const int qcol = (lane & 3) * 2;
#pragma unroll
    for (int mt = 0; mt < 2; mt++) {
#pragma unroll
        for (int nt = 0; nt < 8; nt++) {
            int row = bm + wm * 32 + mt * 16 + qrow;
            int col = bn + wn * 64 + nt * 8 + qcol;
            *(float2*)(C + (size_t)row * HCd + col)       = make_float2(acc[mt][nt][0], acc[mt][nt][1]);
            *(float2*)(C + (size_t)(row + 8) * HCd + col) = make_float2(acc[mt][nt][2], acc[mt][nt][3]);
        }
    }
}

// ---------------- fp32 -> split-bf16 conversion ----------------------------
// mode 0 (A): [hi | lo | hi]; mode 1 (B): [hi | hi | lo]
__global__ __launch_bounds__(256) void k_split(
    const float* __restrict__ S, __nv_bfloat16* __restrict__ D3, int K, int total, int mode)
{
    int i = (blockIdx.x * 256 + threadIdx.x) * 4;
    if (i >= total) return;
    float4 v = *(const float4*)(S + i);
    int m = i / K, k = i - m * K;
    __nv_bfloat16 h[4], l[4];
    float vv[4] = {v.x, v.y, v.z, v.w};
#pragma unroll
    for (int q = 0; q < 4; q++) {
        h[q] = __float2bfloat16(vv[q]);
        l[q] = __float2bfloat16(vv[q] - __bfloat162float(h[q]));
    }
    size_t base = (size_t)m * 3 * K + k;
    __nv_bfloat162 h01, h23, l01, l23;
    h01.x = h[0]; h01.y = h[1]; h23.x = h[2]; h23.y = h[3];
    l01.x = l[0]; l01.y = l[1]; l23.x = l[2]; l23.y = l[3];
    *(__nv_bfloat162*)(D3 + base)     = h01;
    *(__nv_bfloat162*)(D3 + base + 2) = h23;
    if (mode == 0) {
        *(__nv_bfloat162*)(D3 + base + K)         = l01;
        *(__nv_bfloat162*)(D3 + base + K + 2)     = l23;
        *(__nv_bfloat162*)(D3 + base + 2 * K)     = h01;
        *(__nv_bfloat162*)(D3 + base + 2 * K + 2) = h23;
    } else {
        *(__nv_bfloat162*)(D3 + base + K)         = h01;
        *(__nv_bfloat162*)(D3 + base + K + 2)     = h23;
        *(__nv_bfloat162*)(D3 + base + 2 * K)     = l01;
        *(__nv_bfloat162*)(D3 + base + 2 * K + 2) = l23;
    }
}

// ---------------- CSR build -------------------------------------------------
__global__ void k_zero_deg() {
    int i = blockIdx.x * blockDim.x + threadIdx.x;
    if (i < Nn) g_deg[i] = 0;
}

__global__ __launch_bounds__(256) void k_hist(const int* __restrict__ ei) {
    int e = blockIdx.x * blockDim.x + threadIdx.x;
    if (e >= Et) return;
    int d = (e < Ee) ? ei[Ee + e] : (e - Ee);
    atomicAdd(&g_deg[d], 1);
}

__global__ __launch_bounds__(1024) void k_scan() {
    __shared__ int sh[1024];
    int tid = threadIdx.x;
    int base = tid * 8;
    int loc[8];
    int s = 0;
#pragma unroll
    for (int i = 0; i < 8; i++) { loc[i] = s; s += g_deg[base + i]; }
    sh[tid] = s;
    __syncthreads();
    for (int o = 1; o < 1024; o <<= 1) {
        int v = (tid >= o) ? sh[tid - o] : 0;
        __syncthreads();
        sh[tid] += v;
        __syncthreads();
    }
    int pre = tid ? sh[tid - 1] : 0;
#pragma unroll
    for (int i = 0; i < 8; i++) {
        g_off[base + i] = pre + loc[i];
        g_cur[base + i] = pre + loc[i];
    }
    if (tid == 1023) g_off[Nn] = sh[1023];
}

__global__ __launch_bounds__(256) void k_scatter(const int* __restrict__ ei) {
    int e = blockIdx.x * blockDim.x + threadIdx.x;
    if (e >= Et) return;
    int s, d;
    if (e < Ee) { s = ei[e]; d = ei[Ee + e]; } else { s = d = e - Ee; }
    int pos = atomicAdd(&g_cur[d], 1);
    g_src[pos] = s;
}

// ---------------- attention scalars: als/ald [N,H] -------------------------
__global__ __launch_bounds__(256) void k_alphas(
    const float* __restrict__ h, const float* __restrict__ asrc,
    const float* __restrict__ adst)
{
    int w = (blockIdx.x * blockDim.x + threadIdx.x) >> 5;
    int lane = threadIdx.x & 31;
    if (w >= Nn * Hh) return;
    int n = w >> 3, hd = w & 7;
    const float* hp = h + (size_t)n * HCd + hd * Cc;
    const float* sp = asrc + hd * Cc;
    const float* dp = adst + hd * Cc;
    float s1 = 0.0f, s2 = 0.0f;
#pragma unroll
    for (int c = lane; c < Cc; c += 32) {
        float v = hp[c];
        s1 = fmaf(v, sp[c], s1);
        s2 = fmaf(v, dp[c], s2);
    }
#pragma unroll
    for (int o = 16; o; o >>= 1) {
        s1 += __shfl_down_sync(0xffffffffu, s1, o);
        s2 += __shfl_down_sync(0xffffffffu, s2, o);
    }
    if (lane == 0) { g_als[w] = s1; g_ald[w] = s2; }
}

// ---------------- fused softmax + gather aggregation (block per dst) -------
#define CHUNK 64
__global__ __launch_bounds__(256) void k_agg(
    const float* __restrict__ h, const float* __restrict__ bias,
    float* __restrict__ outp, __nv_bfloat16* __restrict__ A3out, int do_norm)
{
    __shared__ int   ssrc[CHUNK];
    __shared__ float salp[CHUNK * 8];
    __shared__ float red[256];
    __shared__ float sm_m[8], sm_iz[8], sm_ald[8];

    int n = blockIdx.x;
    int t = threadIdx.x;
    int st = g_off[n], en = g_off[n + 1];
    int hd = t >> 5;
    int lane = t & 31;

    // ---- pass 1: online softmax stats, warp w handles head w ----
    float aldh = g_ald[n * Hh + hd];
    float m = -3.0e38f, z = 0.0f;
    for (int j = st + lane; j < en; j += 32) {
        int s = g_src[j];
        float l = g_als[s * Hh + hd] + aldh;
        l = (l > 0.0f) ? l : 0.2f * l;
        float mn = fmaxf(m, l);
        z = z * __expf(m - mn) + __expf(l - mn);
        m = mn;
    }
#pragma unroll
    for (int o = 16; o; o >>= 1) {
        float mo = __shfl_xor_sync(0xffffffffu, m, o);
        float zo = __shfl_xor_sync(0xffffffffu, z, o);
        float mn = fmaxf(m, mo);
        z = z * __expf(m - mn) + zo * __expf(mo - mn);
        m = mn;
    }
    if (lane == 0) {
        sm_m[hd]  = m;
        sm_iz[hd] = 1.0f / (z + 1e-16f);
        sm_ald[hd] = aldh;
    }
    __syncthreads();

    // ---- pass 2: chunked aggregation with on-the-fly alphas ----
    float4 acc = make_float4(0.0f, 0.0f, 0.0f, 0.0f);

    for (int j0 = st; j0 < en; j0 += CHUNK) {
        int cnt = min(CHUNK, en - j0);
        __syncthreads();
        if (t < cnt) ssrc[t] = g_src[j0 + t];
        __syncthreads();
        for (int i = t; i < cnt * 8; i += 256) {
            int e = i >> 3, hh2 = i & 7;
            int s = ssrc[e];
            float l = g_als[s * Hh + hh2] + sm_ald[hh2];
            l = (l > 0.0f) ? l : 0.2f * l;
            salp[i] = __expf(l - sm_m[hh2]) * sm_iz[hh2];
        }
        __syncthreads();
#pragma unroll 2
        for (int i = 0; i < cnt; i++) {
            float a = salp[i * 8 + hd];
            float4 v = ((const float4*)(h + (size_t)ssrc[i] * HCd))[t];
            acc.x = fmaf(a, v.x, acc.x);
            acc.y = fmaf(a, v.y, acc.y);
            acc.z = fmaf(a, v.z, acc.z);
            acc.w = fmaf(a, v.w, acc.w);
        }
    }

    float4 b = ((const float4*)bias)[t];
    acc.x = fmaxf(acc.x + b.x, 0.0f);
    acc.y = fmaxf(acc.y + b.y, 0.0f);
    acc.z = fmaxf(acc.z + b.z, 0.0f);
    acc.w = fmaxf(acc.w + b.w, 0.0f);

    if (A3out) {
        float vv[4] = {acc.x, acc.y, acc.z, acc.w};
        __nv_bfloat16 hi[4], lo[4];
#pragma unroll
        for (int q = 0; q < 4; q++) {
            hi[q] = __float2bfloat16(vv[q]);
            lo[q] = __float2bfloat16(vv[q] - __bfloat162float(hi[q]));
        }
        __nv_bfloat162 h01, h23, l01, l23;
        h01.x = hi[0]; h01.y = hi[1]; h23.x = hi[2]; h23.y = hi[3];
        l01.x = lo[0]; l01.y = lo[1]; l23.x = lo[2]; l23.y = lo[3];
        size_t base = (size_t)n * (3 * HCd) + t * 4;
        *(__nv_bfloat162*)(A3out + base)               = h01;
        *(__nv_bfloat162*)(A3out + base + 2)           = h23;
        *(__nv_bfloat162*)(A3out + base + HCd)         = l01;
        *(__nv_bfloat162*)(A3out + base + HCd + 2)     = l23;
        *(__nv_bfloat162*)(A3out + base + 2 * HCd)     = h01;
        *(__nv_bfloat162*)(A3out + base + 2 * HCd + 2) = h23;
        return;
    }

    if (do_norm) {
        float s = acc.x * acc.x + acc.y * acc.y + acc.z * acc.z + acc.w * acc.w;
        red[t] = s;
        __syncthreads();
        for (int o = 128; o; o >>= 1) {
            if (t < o) red[t] += red[t + o];
            __syncthreads();
        }
        float nrm = fmaxf(sqrtf(red[0]), 1e-12f);
        float iv = 1.0f / nrm;
        acc.x *= iv; acc.y *= iv; acc.z *= iv; acc.w *= iv;
    }

    ((float4*)(outp + (size_t)n * HCd))[t] = acc;
}

// ---------------- node MLP: hn[1024] -> 32 -> 32 -> 32 (relu) --------------
__global__ __launch_bounds__(256) void k_small_mlp(
    const float* __restrict__ hn,
    const float* __restrict__ Ws1, const float* __restrict__ bs1,
    const float* __restrict__ Ws2, const float* __restrict__ bs2,
    const float* __restrict__ Ws3, const float* __restrict__ bs3)
{
    __shared__ float wst[32][33];
    int lane = threadIdx.x & 31;
    int wrp  = threadIdx.x >> 5;
    int n = blockIdx.x * 8 + wrp;
    const float* row = hn + (size_t)n * HCd;

    float acc = bs1[lane];
    int j  = threadIdx.x >> 3;
    int kk = threadIdx.x & 7;
    for (int k0 = 0; k0 < HCd; k0 += 32) {
        __syncthreads();
        wst[kk +  0][j] = Ws1[j * HCd + k0 + kk +  0];
        wst[kk +  8][j] = Ws1[j * HCd + k0 + kk +  8];
        wst[kk + 16][j] = Ws1[j * HCd + k0 + kk + 16];
        wst[kk + 24][j] = Ws1[j * HCd + k0 + kk + 24];
        __syncthreads();
        float rv = row[k0 + lane];
#pragma unroll
        for (int q = 0; q < 32; q++) {
            float r = __shfl_sync(0xffffffffu, rv, q);
            acc = fmaf(r, wst[q][lane], acc);
        }
    }
    acc = fmaxf(acc, 0.0f);

    float a2 = bs2[lane];
#pragma unroll
    for (int i = 0; i < 32; i++)
        a2 = fmaf(Ws2[lane * 32 + i], __shfl_sync(0xffffffffu, acc, i), a2);
    a2 = fmaxf(a2, 0.0f);

    float a3 = bs3[lane];
#pragma unroll
    for (int i = 0; i < 32; i++)
        a3 = fmaf(Ws3[lane * 32 + i], __shfl_sync(0xffffffffu, a2, i), a3);
    a3 = fmaxf(a3, 0.0f);

    g_gs[n * 32 + lane] = a3;
}

// ---------------- per-graph Gram: HH[g][d][e] ------------------------------
__global__ __launch_bounds__(1024) void k_gram(float* __restrict__ out) {
    int g = blockIdx.x;
    __shared__ float sg[128][33];
    int d  = threadIdx.x >> 5;
    int e1 = threadIdx.x & 31;
    float acc = 0.0f;
    for (int n0 = 0; n0 < NPGd; n0 += 128) {
        __syncthreads();
        for (int i = threadIdx.x; i < 128 * 32; i += 1024) {
            int r = i >> 5, c = i & 31;
            sg[r][c] = g_gs[(size_t)(g * NPGd + n0 + r) * 32 + c];
        }
        __syncthreads();
#pragma unroll 8
        for (int r = 0; r < 128; r++) acc = fmaf(sg[r][d], sg[r][e1], acc);
    }
    out[g * 1024 + d * 32 + e1] = acc;
}

// ---------------- head MLP: HH[1024] -> 32 -> 32 -> 2 ----------------------
__global__ __launch_bounds__(32) void k_head_mlp(
    const float* __restrict__ HHin,
    const float* __restrict__ Wm1, const float* __restrict__ bm1,
    const float* __restrict__ Wm2, const float* __restrict__ bm2,
    const float* __restrict__ Wm3, const float* __restrict__ bm3,
    float* __restrict__ oout)
{
    int g = blockIdx.x;
    int jj = threadIdx.x;
    const float* hh = HHin + g * 1024;
    float acc = bm1[jj];
    for (int k = 0; k < 1024; k++) acc = fmaf(hh[k], Wm1[jj * 1024 + k], acc);
    acc = fmaxf(acc, 0.0f);

    float a2 = bm2[jj];
#pragma unroll
    for (int i = 0; i < 32; i++)
        a2 = fmaf(Wm2[jj * 32 + i], __shfl_sync(0xffffffffu, acc, i), a2);
    a2 = fmaxf(a2, 0.0f);

    float a3 = (jj < 2) ? bm3[jj] : 0.0f;
#pragma unroll
    for (int i = 0; i < 32; i++) {
        float v = __shfl_sync(0xffffffffu, a2, i);
        if (jj < 2) a3 = fmaf(Wm3[jj * 32 + i], v, a3);
    }
    if (jj < 2) oout[g * 2 + jj] = fmaxf(a3, 0.0f);
}

// ---------------- launch ----------------------------------------------------
extern "C" void kernel_launch(void* const* d_in, const int* in_sizes, int n_in,
                              void* d_out, int out_size)
{
    const float* x   = (const float*)d_in[0];
    const int*   ei  = (const int*)  d_in[1];
    const float* W1  = (const float*)d_in[2];
    const float* as1 = (const float*)d_in[3];
    const float* ad1 = (const float*)d_in[4];
    const float* b1  = (const float*)d_in[5];
    const float* W2  = (const float*)d_in[6];
    const float* as2 = (const float*)d_in[7];
    const float* ad2 = (const float*)d_in[8];
    const float* b2  = (const float*)d_in[9];
    const float* Ws1 = (const float*)d_in[10];
    const float* bs1 = (const float*)d_in[11];
    const float* Ws2 = (const float*)d_in[12];
    const float* bs2 = (const float*)d_in[13];
    const float* Ws3 = (const float*)d_in[14];
    const float* bs3 = (const float*)d_in[15];
    const float* Wm1 = (const float*)d_in[16];
    const float* bm1 = (const float*)d_in[17];
    const float* Wm2 = (const float*)d_in[18];
    const float* bm2 = (const float*)d_in[19];
    const float* Wm3 = (const float*)d_in[20];
    const float* bm3 = (const float*)d_in[21];
    float* out = (float*)d_out;

    float *lin, *feat;
    __nv_bfloat16 *A3, *B3, *B3b;
    cudaGetSymbolAddress((void**)&lin,  g_lin);
    cudaGetSymbolAddress((void**)&feat, g_feat);
    cudaGetSymbolAddress((void**)&A3,   g_A3);
    cudaGetSymbolAddress((void**)&B3,   g_B3);
    cudaGetSymbolAddress((void**)&B3b,  g_B3b);
    (void)in_sizes; (void)n_in; (void)out_size;

    static cudaStream_t s2 = nullptr;
    static cudaEvent_t  evFork = nullptr, evJoin = nullptr;
    if (!s2) {
        cudaFuncSetAttribute(gemm_mma, cudaFuncAttributeMaxDynamicSharedMemorySize, GT_DSMEM);
        cudaStreamCreateWithFlags(&s2, cudaStreamNonBlocking);
        cudaEventCreateWithFlags(&evFork, cudaEventDisableTiming);
        cudaEventCreateWithFlags(&evJoin, cudaEventDisableTiming);
    }

    const int EB = (Et + 255) / 256;

    // ---- fork: side stream does CSR build + W2 split (off critical path) ----
    cudaEventRecord(evFork, 0);
    cudaStreamWaitEvent(s2, evFork, 0);
    k_zero_deg<<<(Nn + 255) / 256, 256, 0, s2>>>();
    k_hist<<<EB, 256, 0, s2>>>(ei);
    k_scan<<<1, 1024, 0, s2>>>();
    k_scatter<<<EB, 256, 0, s2>>>(ei);
    k_split<<<(HCd * HCd / 4 + 255) / 256, 256, 0, s2>>>(W2, B3b, HCd, HCd * HCd, 1);
    cudaEventRecord(evJoin, s2);

    // ---- main stream: layer-1 splits + GEMM + alphas ----
    k_split<<<(Nn * FIN / 4 + 255) / 256, 256>>>(x,  A3, FIN, Nn * FIN, 0);
    k_split<<<(HCd * FIN / 4 + 255) / 256, 256>>>(W1, B3, FIN, HCd * FIN, 1);
    gemm_mma<<<dim3(HCd / 128, Nn / 128), 256, GT_DSMEM>>>(A3, B3, lin, 3 * FIN);
    k_alphas<<<(Nn * Hh * 32) / 256, 256>>>(lin, as1, ad1);

    // ---- join: k_agg needs CSR; GEMM-2 needs B3b ----
    cudaStreamWaitEvent(0, evJoin, 0);
    k_agg<<<Nn, 256>>>(lin, b1, nullptr, A3, 0);   // fused softmax; split-bf16 h1 out

    // ---- GAT layer 2 (K' = 3072) ----
    gemm_mma<<<dim3(HCd / 128, Nn / 128), 256, GT_DSMEM>>>(A3, B3b, lin, 3 * HCd);
    k_alphas<<<(Nn * Hh * 32) / 256, 256>>>(lin, as2, ad2);
    k_agg<<<Nn, 256>>>(lin, b2, feat, nullptr, 1); // fused softmax; normalize + fp32

    // ---- node MLP + Gram + head MLP ----
    k_small_mlp<<<Nn / 8, 256>>>(feat, Ws1, bs1, Ws2, bs2, Ws3, bs3);
    k_gram<<<Gg, 1024>>>(out);
    k_head_mlp<<<Gg, 32>>>(out, Wm1, bm1, Wm2, bm2, Wm3, bm3, out + Gg * 1024);
}